// round 14
// baseline (speedup 1.0000x reference)
#include <cuda_runtime.h>
#include <cuda_fp16.h>
#include <math.h>
#include <cstdint>

// Problem constants
#define BB 4
#define SS 2048
#define EE 1024
#define HH 16
#define DD 64
#define MM (BB * SS)   // 8192
#define NN 1024
#define KK 1024

// Scratch (device globals — no cudaMalloc allowed)
__device__ __half g_q[BB * HH * SS * DD];    // [b][h][s][d]
__device__ __half g_k[BB * HH * SS * DD];    // [b][h][s][d]
__device__ __half g_v[BB * HH * SS * DD];    // TRANSPOSED: [b][h][d][s]
__device__ __half g_attn[MM * EE];           // [b][s][h*64+d]
__device__ __half g_xa[MM * KK];             // x as fp16
__device__ __half g_wt3[3 * NN * KK];        // Wq|Wk|Wv transposed [3N][K] fp16
__device__ __half g_wt[NN * KK];             // Wp transposed [N][K] fp16

// ---------------------------------------------------------------------------
// helpers
// ---------------------------------------------------------------------------
__device__ __forceinline__ uint32_t smem_u32(const void* p) {
    uint32_t a;
    asm("{ .reg .u64 t; cvta.to.shared.u64 t, %1; cvt.u32.u64 %0, t; }" : "=r"(a) : "l"(p));
    return a;
}
__device__ __forceinline__ float ex2(float x) {
    float y;
    asm("ex2.approx.ftz.f32 %0, %1;" : "=f"(y) : "f"(x));
    return y;
}
__device__ __forceinline__ void cp16(uint32_t dst, const void* src) {
    asm volatile("cp.async.ca.shared.global [%0], [%1], 16;" :: "r"(dst), "l"(src));
}
__device__ __forceinline__ void ldm4(uint32_t* r, uint32_t addr) {
    asm volatile("ldmatrix.sync.aligned.m8n8.x4.shared.b16 {%0,%1,%2,%3}, [%4];"
                 : "=r"(r[0]), "=r"(r[1]), "=r"(r[2]), "=r"(r[3]) : "r"(addr));
}
__device__ __forceinline__ void mma_f16(float* c, const uint32_t* a, const uint32_t* b) {
    asm volatile(
        "mma.sync.aligned.m16n8k16.row.col.f32.f16.f16.f32 "
        "{%0,%1,%2,%3}, {%4,%5,%6,%7}, {%8,%9}, {%0,%1,%2,%3};"
        : "+f"(c[0]), "+f"(c[1]), "+f"(c[2]), "+f"(c[3])
        : "r"(a[0]), "r"(a[1]), "r"(a[2]), "r"(a[3]), "r"(b[0]), "r"(b[1]));
}
__device__ __forceinline__ uint32_t packh2(float a, float b) {
    __half2 h = __floats2half2_rn(a, b);
    return *(uint32_t*)&h;
}

// ---------------------------------------------------------------------------
// fp16 mma.sync GEMM: 128 threads (4 warps, 2x2 grid of 64x64 warp tiles),
// CTA 128x128, BK=64 (128B/row), 3-stage cp.async, 144B smem rows.
// NEW (R14): register double-buffered fragments — ldm4 for k2+1 issued
// before the MMAs of k2; k2=0 frags preloaded right after the stage barrier
// (ahead of the cp.async burst) to hide LDSM latency at 2 warps/SMSP.
// MODE 0: out fp32 row-major [M,NN], bias=b0
// MODE 1: fused QKV, Ncols=3072: n>>10 selects {Q,K,V}; V stored [B][H][D][S]
// ---------------------------------------------------------------------------
#define SROWB 144
#define SBUF (128 * SROWB)      // 18432 per matrix per stage
#define SSTAGE (2 * SBUF)       // 36864
#define SNSTG 3
#define SNKS (KK / 64)          // 16

template <int MODE>
__global__ void __launch_bounds__(128) tc_gemm_kernel(
    const __half* __restrict__ A, const __half* __restrict__ Bt,
    const float* __restrict__ b0, const float* __restrict__ b1,
    const float* __restrict__ b2,
    void* __restrict__ o0, __half* __restrict__ o1, __half* __restrict__ o2)
{
    extern __shared__ char smc[];
    const uint32_t dat_u = smem_u32(smc);

    const int tid = threadIdx.x;
    const int wid = tid >> 5;
    const int lane = tid & 31;
    const int g = lane >> 2;
    const int t = lane & 3;
    const int wm = wid >> 1;     // 0..1
    const int wn = wid & 1;      // 0..1
    const int bm = blockIdx.y * 128;
    const int bn = blockIdx.x * 128;

    const int lq = tid & 7;
    const int lr = tid >> 3;     // 0..15

    const uint32_t aoff = (uint32_t)((wm * 64 + (lane & 15)) * SROWB + ((lane >> 4) << 4));
    const uint32_t boff = (uint32_t)((wn * 64 + ((lane >> 4) << 3) + (lane & 7)) * SROWB
                                     + (((lane >> 3) & 1) << 4));

    float acc[4][8][4];
#pragma unroll
    for (int mt = 0; mt < 4; mt++)
#pragma unroll
        for (int nt = 0; nt < 8; nt++)
#pragma unroll
            for (int r = 0; r < 4; r++) acc[mt][nt][r] = 0.f;

    // prologue: stages 0,1
#pragma unroll
    for (int s = 0; s < SNSTG - 1; ++s) {
        const uint32_t sb = dat_u + s * SSTAGE;
        const int kof = s * 64;
#pragma unroll
        for (int i = 0; i < 8; ++i) {
            int row = lr + i * 16;
            cp16(sb + row * SROWB + lq * 16, A + (size_t)(bm + row) * KK + kof + lq * 8);
            cp16(sb + SBUF + row * SROWB + lq * 16, Bt + (size_t)(bn + row) * KK + kof + lq * 8);
        }
        asm volatile("cp.async.commit_group;" ::: "memory");
    }

    for (int ks = 0; ks < SNKS; ++ks) {
        asm volatile("cp.async.wait_group %0;" :: "n"(SNSTG - 2) : "memory");
        __syncthreads();

        const uint32_t aB = dat_u + (ks % SNSTG) * SSTAGE;
        const uint32_t bB = aB + SBUF;

        // fragment double-buffer; preload k2=0 BEFORE the cp.async burst
        uint32_t af[2][4][4], bf[2][4][4];
#pragma unroll
        for (int mt = 0; mt < 4; mt++)
            ldm4(af[0][mt], aB + aoff + mt * (16 * SROWB));
#pragma unroll
        for (int p = 0; p < 4; p++)
            ldm4(bf[0][p], bB + boff + p * (16 * SROWB));

        // issue next-stage global loads
        const int ldk = ks + SNSTG - 1;
        if (ldk < SNKS) {
            const uint32_t sb = dat_u + (ldk % SNSTG) * SSTAGE;
            const int kof = ldk * 64;
#pragma unroll
            for (int i = 0; i < 8; ++i) {
                int row = lr + i * 16;
                cp16(sb + row * SROWB + lq * 16, A + (size_t)(bm + row) * KK + kof + lq * 8);
                cp16(sb + SBUF + row * SROWB + lq * 16, Bt + (size_t)(bn + row) * KK + kof + lq * 8);
            }
        }
        asm volatile("cp.async.commit_group;" ::: "memory");   // ALWAYS (FIFO count)

#pragma unroll
        for (int k2 = 0; k2 < 4; ++k2) {
            const int cur = k2 & 1;
            const int nxt = cur ^ 1;
            if (k2 < 3) {   // prefetch next k-step's fragments before MMAs
#pragma unroll
                for (int mt = 0; mt < 4; mt++)
                    ldm4(af[nxt][mt], aB + aoff + mt * (16 * SROWB) + (k2 + 1) * 32);
#pragma unroll
                for (int p = 0; p < 4; p++)
                    ldm4(bf[nxt][p], bB + boff + p * (16 * SROWB) + (k2 + 1) * 32);
            }
#pragma unroll
            for (int mt = 0; mt < 4; mt++)
#pragma unroll
                for (int p = 0; p < 4; p++) {
                    mma_f16(acc[mt][2 * p],     af[cur][mt], bf[cur][p] + 0);
                    mma_f16(acc[mt][2 * p + 1], af[cur][mt], bf[cur][p] + 2);
                }
        }
    }

    // epilogue
#pragma unroll
    for (int mt = 0; mt < 4; mt++) {
#pragma unroll
        for (int half_ = 0; half_ < 2; half_++) {
            int m = bm + wm * 64 + mt * 16 + g + half_ * 8;
            int b = m >> 11;
            int s = m & 2047;
#pragma unroll
            for (int nt = 0; nt < 8; nt++) {
                int n = bn + wn * 64 + nt * 8 + 2 * t;
                float v0 = acc[mt][nt][half_ * 2 + 0];
                float v1 = acc[mt][nt][half_ * 2 + 1];
                if (MODE == 0) {
                    v0 += __ldg(&b0[n]); v1 += __ldg(&b0[n + 1]);
                    float* op = (float*)o0 + (size_t)m * NN + n;
                    *(float2*)op = make_float2(v0, v1);
                } else {
                    int which = n >> 10;
                    int nh = n & 1023;
                    int h = nh >> 6, d0 = nh & 63;
                    const float* bptr = which == 0 ? b0 : (which == 1 ? b1 : b2);
                    v0 += __ldg(&bptr[nh]); v1 += __ldg(&bptr[nh + 1]);
                    if (which == 2) {   // V transposed [b][h][d][s]
                        size_t bhd = (((size_t)b * HH + h) * DD + d0) * SS + s;
                        o2[bhd] = __float2half_rn(v0);
                        o2[bhd + SS] = __float2half_rn(v1);
                    } else {
                        __half* dst = which == 0 ? (__half*)o0 : o1;
                        __half* op = dst + (((size_t)b * HH + h) * SS + s) * DD + d0;
                        *(__half2*)op = __floats2half2_rn(v0, v1);
                    }
                }
            }
        }
    }
}

// ---------------------------------------------------------------------------
// prep kernels
// ---------------------------------------------------------------------------
__global__ void cvt_half_kernel(const float4* __restrict__ in, __half2* __restrict__ outp, int n4)
{
    for (int i = blockIdx.x * blockDim.x + threadIdx.x; i < n4; i += gridDim.x * blockDim.x) {
        float4 v = in[i];
        outp[2 * i]     = __floats2half2_rn(v.x, v.y);
        outp[2 * i + 1] = __floats2half2_rn(v.z, v.w);
    }
}

// fused QKV weight transpose: z in [0,48) -> which=z>>4 selects Wq/Wk/Wv,
// b=z&15 is the head. in fp32 [16][E][D] -> out half [which][16][D][E]
__global__ void transpose3_h_kernel(const float* __restrict__ wq,
                                    const float* __restrict__ wk,
                                    const float* __restrict__ wv,
                                    __half* __restrict__ outp)
{
    __shared__ float tile[32][33];
    const int z = blockIdx.z;
    const int which = z >> 4;
    const int b = z & 15;
    const float* in = (which == 0 ? wq : (which == 1 ? wk : wv));
    const int c0 = blockIdx.x * 32, r0 = blockIdx.y * 32;
    const int tx = threadIdx.x, ty = threadIdx.y;
    const float* inb = in + (size_t)b * EE * DD;
#pragma unroll
    for (int j = 0; j < 32; j += 8)
        tile[ty + j][tx] = inb[(size_t)(r0 + ty + j) * DD + c0 + tx];
    __syncthreads();
    __half* ob = outp + (size_t)z * DD * EE;
#pragma unroll
    for (int j = 0; j < 32; j += 8)
        ob[(size_t)(c0 + ty + j) * EE + r0 + tx] = __float2half_rn(tile[tx][ty + j]);
}

// in fp32 [R][C] -> out half [C][R]  (Wp)
__global__ void transpose_h_kernel(const float* __restrict__ in, __half* __restrict__ outp,
                                   int R, int C)
{
    __shared__ float tile[32][33];
    const int c0 = blockIdx.x * 32, r0 = blockIdx.y * 32;
    const int tx = threadIdx.x, ty = threadIdx.y;
#pragma unroll
    for (int j = 0; j < 32; j += 8)
        tile[ty + j][tx] = in[(size_t)(r0 + ty + j) * C + c0 + tx];
    __syncthreads();
#pragma unroll
    for (int j = 0; j < 32; j += 8)
        outp[(size_t)(c0 + ty + j) * R + r0 + tx] = __float2half_rn(tile[tx][ty + j]);
}

// ---------------------------------------------------------------------------
// Flash attention (causal) fp16 mma. Br=128, Bc=64, 256 threads (8 warps,
// 16 rows each). Q frags in registers; score C-frags reused as PV A-frags.
// K/Vt double-buffered cp.async. smem rows 144B.  (unchanged from R13)
// ---------------------------------------------------------------------------
#define FROWB 144
#define FTILE (64 * FROWB)      // 9216  (one 64-row K or Vt tile)
#define QTILE (128 * FROWB)     // 18432

__global__ void __launch_bounds__(256) flash_mma_kernel(
    const __half* __restrict__ q, const __half* __restrict__ k,
    const __half* __restrict__ vt, __half* __restrict__ outp)
{
    extern __shared__ char smc[];
    const uint32_t smb = smem_u32(smc);
    const uint32_t QsB = smb;
    const uint32_t KB0 = smb + QTILE;    // buffers: [K|Vt] x2

    const int qi = blockIdx.x;           // 0..15, rows [128qi, 128qi+128)
    const int bh = blockIdx.y;
    const size_t base = (size_t)bh * SS * DD;
    const int tid = threadIdx.x;
    const int w = tid >> 5;
    const int lane = tid & 31;
    const int g = lane >> 2;
    const int t = tid & 3;
    const int qr0 = qi * 128;
    const int r0g = w * 16 + g;          // local row of c0/c1; +8 for c2/c3
    const int nj = 2 * qi + 2;           // number of 64-wide K tiles

    const uint32_t qoff = (uint32_t)((w * 16 + (lane & 15)) * FROWB + ((lane >> 4) << 4));
    const uint32_t kvoff = (uint32_t)(((((lane >> 4) << 3) + (lane & 7)) * FROWB)
                                      + (((lane >> 3) & 1) << 4));

    // load Q tile (128 rows)
    for (int idx = tid; idx < 128 * 8; idx += 256) {
        int r = idx >> 3, qc = idx & 7;
        *(uint4*)(smc + r * FROWB + qc * 16) =
            *(const uint4*)(q + base + (size_t)(qr0 + r) * DD + qc * 8);
    }

    // prefetch K/Vt tile j=0 into buffer 0
    {
        const uint32_t kb = KB0, vb = KB0 + FTILE;
        for (int idx = tid; idx < 128 * 8; idx += 256) {
            int m = idx >> 3, qc = idx & 7;
            if (m < 64)
                cp16(kb + m * FROWB + qc * 16, k + base + (size_t)m * DD + qc * 8);
            else
                cp16(vb + (m - 64) * FROWB + qc * 16, vt + base + (size_t)(m - 64) * SS + qc * 8);
        }
        asm volatile("cp.async.commit_group;" ::: "memory");
    }
    __syncthreads();   // Q visible

    uint32_t qf[4][4];
#pragma unroll
    for (int ks = 0; ks < 4; ks++) ldm4(qf[ks], QsB + qoff + ks * 32);

    float o[8][4];
#pragma unroll
    for (int dt = 0; dt < 8; dt++)
#pragma unroll
        for (int r = 0; r < 4; r++) o[dt][r] = 0.f;
    float m0 = -1e30f, m1 = -1e30f, l0 = 0.f, l1 = 0.f;
    const float sc = 0.125f * 1.4426950408889634f;

    for (int j = 0; j < nj; ++j) {
        asm volatile("cp.async.wait_group 0;" ::: "memory");
        __syncthreads();
        const uint32_t kb = KB0 + (j & 1) * 2 * FTILE;
        const uint32_t vb = kb + FTILE;

        if (j + 1 < nj) {   // prefetch next tile
            const uint32_t kb2 = KB0 + ((j + 1) & 1) * 2 * FTILE;
            const uint32_t vb2 = kb2 + FTILE;
            const size_t koff = base + (size_t)(j + 1) * 64 * DD;
            const size_t voff = base + (size_t)(j + 1) * 64;
            for (int idx = tid; idx < 128 * 8; idx += 256) {
                int m = idx >> 3, qc = idx & 7;
                if (m < 64)
                    cp16(kb2 + m * FROWB + qc * 16, k + koff + (size_t)m * DD + qc * 8);
                else
                    cp16(vb2 + (m - 64) * FROWB + qc * 16, vt + voff + (size_t)(m - 64) * SS + qc * 8);
            }
            asm volatile("cp.async.commit_group;" ::: "memory");
        }

        // ---- S = Q K^T ----
        float sa[8][4];
#pragma unroll
        for (int nt = 0; nt < 8; nt++)
#pragma unroll
            for (int r = 0; r < 4; r++) sa[nt][r] = 0.f;
#pragma unroll
        for (int ks = 0; ks < 4; ++ks) {
#pragma unroll
            for (int p = 0; p < 4; p++) {
                uint32_t kf[4];
                ldm4(kf, kb + kvoff + p * (16 * FROWB) + ks * 32);
                mma_f16(sa[2 * p],     qf[ks], kf + 0);
                mma_f16(sa[2 * p + 1], qf[ks], kf + 2);
            }
        }

        // ---- fragment softmax ----
        const bool maskT = (j >= 2 * qi);   // only last two tiles touch diagonal
        const int row0 = r0g;               // local row (c0/c1)
        const int colb = (j - 2 * qi) * 64; // local col base for diagonal tiles
        float mloc0 = -1e30f, mloc1 = -1e30f;
#pragma unroll
        for (int nt = 0; nt < 8; nt++) {
            sa[nt][0] *= sc; sa[nt][1] *= sc; sa[nt][2] *= sc; sa[nt][3] *= sc;
            if (maskT) {
                int col = colb + nt * 8 + 2 * t;
                if (col     > row0)     sa[nt][0] = -1e30f;
                if (col + 1 > row0)     sa[nt][1] = -1e30f;
                if (col     > row0 + 8) sa[nt][2] = -1e30f;
                if (col + 1 > row0 + 8) sa[nt][3] = -1e30f;
            }
            mloc0 = fmaxf(mloc0, fmaxf(sa[nt][0], sa[nt][1]));
            mloc1 = fmaxf(mloc1, fmaxf(sa[nt][2], sa[nt][3]));
        }
        mloc0 = fmaxf(mloc0, __shfl_xor_sync(0xffffffffu, mloc0, 1));
        mloc0 = fmaxf(mloc0, __shfl_xor_sync(0xffffffffu, mloc0, 2));
        mloc1 = fmaxf(mloc1, __shfl_xor_sync(0xffffffffu, mloc1, 1));
        mloc1 = fmaxf(mloc1, __shfl_xor_sync(0xffffffffu, mloc1, 2));

        float mn0 = fmaxf(m0, mloc0), mn1 = fmaxf(m1, mloc1);
        float al0 = ex2(m0 - mn0), al1 = ex2(m1 - mn1);
        float rs0 = 0.f, rs1 = 0.f;
#pragma unroll
        for (int nt = 0; nt < 8; nt++) {
            sa[nt][0] = ex2(sa[nt][0] - mn0);
            sa[nt][1] = ex2(sa[nt][1] - mn0);
            sa[nt][2] = ex2(sa[nt][2] - mn1);
            sa[nt][3] = ex2(sa[nt][3] - mn1);
            rs0 += sa[nt][0] + sa[nt][1];
            rs1 += sa[nt][2] + sa[nt][3];
        }
        rs0 += __shfl_xor_sync(0xffffffffu, rs0, 1);
        rs0 += __shfl_xor_sync(0xffffffffu, rs0, 2);
        rs1 += __shfl_xor_sync(0xffffffffu, rs1, 1);
        rs1 += __shfl_xor_sync(0xffffffffu, rs1, 2);
        l0 = l0 * al0 + rs0;
        l1 = l1 * al1 + rs1;
        m0 = mn0; m1 = mn1;
#pragma unroll
        for (int dt = 0; dt < 8; dt++) {
            o[dt][0] *= al0; o[dt][1] *= al0;
            o[dt][2] *= al1; o[dt][3] *= al1;
        }

        // ---- O += P V : score C-frag is the A-frag ----
#pragma unroll
        for (int ks = 0; ks < 4; ++ks) {
            uint32_t pf[4];
            pf[0] = packh2(sa[2 * ks][0],     sa[2 * ks][1]);
            pf[1] = packh2(sa[2 * ks][2],     sa[2 * ks][3]);
            pf[2] = packh2(sa[2 * ks + 1][0], sa[2 * ks + 1][1]);
            pf[3] = packh2(sa[2 * ks + 1][2], sa[2 * ks + 1][3]);
#pragma unroll
            for (int p = 0; p < 4; p++) {
                uint32_t vf[4];
                ldm4(vf, vb + kvoff + p * (16 * FROWB) + ks * 32);
                mma_f16(o[2 * p],     pf, vf + 0);
                mma_f16(o[2 * p + 1], pf, vf + 2);
            }
        }
    }

    // epilogue: normalize, write half to [B, S, H*D]
    const int b = bh >> 4;
    const int h = bh & 15;
    const float inv0 = 1.f / l0, inv1 = 1.f / l1;
    const int grow0 = qr0 + r0g, grow1 = grow0 + 8;
#pragma unroll
    for (int nt = 0; nt < 8; nt++) {
        int d = nt * 8 + 2 * t;
        size_t ob0 = ((size_t)b * SS + grow0) * EE + h * 64 + d;
        size_t ob1 = ((size_t)b * SS + grow1) * EE + h * 64 + d;
        *(__half2*)&outp[ob0] = __floats2half2_rn(o[nt][0] * inv0, o[nt][1] * inv0);
        *(__half2*)&outp[ob1] = __floats2half2_rn(o[nt][2] * inv1, o[nt][3] * inv1);
    }
}

// ---------------------------------------------------------------------------
extern "C" void kernel_launch(void* const* d_in, const int* in_sizes, int n_in,
                              void* d_out, int out_size)
{
    const float* x  = (const float*)d_in[0];
    const float* Wq = (const float*)d_in[1];
    const float* bq = (const float*)d_in[2];
    const float* Wk = (const float*)d_in[3];
    const float* bk = (const float*)d_in[4];
    const float* Wv = (const float*)d_in[5];
    const float* bv = (const float*)d_in[6];
    const float* Wp = (const float*)d_in[7];
    const float* bp = (const float*)d_in[8];
    float* out = (float*)d_out;

    __half *qp, *kp, *vp, *ap, *xap, *wtp, *wt3p;
    cudaGetSymbolAddress((void**)&qp, g_q);
    cudaGetSymbolAddress((void**)&kp, g_k);
    cudaGetSymbolAddress((void**)&vp, g_v);
    cudaGetSymbolAddress((void**)&ap, g_attn);
    cudaGetSymbolAddress((void**)&xap, g_xa);
    cudaGetSymbolAddress((void**)&wtp, g_wt);
    cudaGetSymbolAddress((void**)&wt3p, g_wt3);

    const int gemm_smem = SNSTG * SSTAGE;                  // 110592
    cudaFuncSetAttribute(tc_gemm_kernel<0>, cudaFuncAttributeMaxDynamicSharedMemorySize, gemm_smem);
    cudaFuncSetAttribute(tc_gemm_kernel<1>, cudaFuncAttributeMaxDynamicSharedMemorySize, gemm_smem);
    const int fl_smem = QTILE + 4 * FTILE;                 // 55296
    cudaFuncSetAttribute(flash_mma_kernel, cudaFuncAttributeMaxDynamicSharedMemorySize, fl_smem);

    cvt_half_kernel<<<1024, 256>>>((const float4*)x, (__half2*)xap, MM * KK / 4);

    dim3 tb(32, 8);
    transpose3_h_kernel<<<dim3(2, 32, 48), tb>>>(Wq, Wk, Wv, wt3p);
    transpose_h_kernel<<<dim3(32, 32, 1), tb>>>(Wp, wtp, EE, EE);

    // fused QKV: N = 3072
    tc_gemm_kernel<1><<<dim3(24, 64), 128, gemm_smem>>>(
        xap, wt3p, bq, bk, bv, qp, kp, vp);

    dim3 fg(SS / 128, BB * HH);   // (16, 64)
    flash_mma_kernel<<<fg, 256, fl_smem>>>(qp, kp, vp, ap);

    // output projection
    tc_gemm_kernel<0><<<dim3(8, 64), 128, gemm_smem>>>(
        ap, wtp, bp, bp, bp, out, nullptr, nullptr);
}

// round 16
// speedup vs baseline: 1.0831x; 1.0831x over previous
#include <cuda_runtime.h>
#include <cuda_fp16.h>
#include <math.h>
#include <cstdint>

// Problem constants
#define BB 4
#define SS 2048
#define EE 1024
#define HH 16
#define DD 64
#define MM (BB * SS)   // 8192
#define NN 1024
#define KK 1024

// Scratch (device globals — no cudaMalloc allowed)
__device__ __half g_q[BB * HH * SS * DD];    // [b][h][s][d]
__device__ __half g_k[BB * HH * SS * DD];    // [b][h][s][d]
__device__ __half g_v[BB * HH * SS * DD];    // TRANSPOSED: [b][h][d][s]
__device__ __half g_attn[MM * EE];           // [b][s][h*64+d]
__device__ __half g_xa[MM * KK];             // x as fp16
__device__ __half g_wt3[3 * NN * KK];        // Wq|Wk|Wv transposed [3N][K] fp16
__device__ __half g_wt[NN * KK];             // Wp transposed [N][K] fp16

// ---------------------------------------------------------------------------
// helpers
// ---------------------------------------------------------------------------
__device__ __forceinline__ uint32_t smem_u32(const void* p) {
    uint32_t a;
    asm("{ .reg .u64 t; cvta.to.shared.u64 t, %1; cvt.u32.u64 %0, t; }" : "=r"(a) : "l"(p));
    return a;
}
__device__ __forceinline__ float ex2(float x) {
    float y;
    asm("ex2.approx.ftz.f32 %0, %1;" : "=f"(y) : "f"(x));
    return y;
}
__device__ __forceinline__ void cp16(uint32_t dst, const void* src) {
    asm volatile("cp.async.ca.shared.global [%0], [%1], 16;" :: "r"(dst), "l"(src));
}
__device__ __forceinline__ void ldm4(uint32_t* r, uint32_t addr) {
    asm volatile("ldmatrix.sync.aligned.m8n8.x4.shared.b16 {%0,%1,%2,%3}, [%4];"
                 : "=r"(r[0]), "=r"(r[1]), "=r"(r[2]), "=r"(r[3]) : "r"(addr));
}
__device__ __forceinline__ void mma_f16(float* c, const uint32_t* a, const uint32_t* b) {
    asm volatile(
        "mma.sync.aligned.m16n8k16.row.col.f32.f16.f16.f32 "
        "{%0,%1,%2,%3}, {%4,%5,%6,%7}, {%8,%9}, {%0,%1,%2,%3};"
        : "+f"(c[0]), "+f"(c[1]), "+f"(c[2]), "+f"(c[3])
        : "r"(a[0]), "r"(a[1]), "r"(a[2]), "r"(a[3]), "r"(b[0]), "r"(b[1]));
}
__device__ __forceinline__ uint32_t packh2(float a, float b) {
    __half2 h = __floats2half2_rn(a, b);
    return *(uint32_t*)&h;
}

// ---------------------------------------------------------------------------
// fp16 mma.sync GEMM: 128 threads (4 warps, 2x2 grid of 64x64 warp tiles),
// CTA 128x128, BK=64 (128B/row), 3-stage cp.async, 144B smem rows.
// R14: register double-buffered ldmatrix fragments.
// R15: cp.async burst interleaved INTO the k2 loop (4 cp16 per k16 step,
// issued between fragment prefetch and MMAs) so LSU work overlaps tensor
// work instead of serializing before it.
// MODE 0: out fp32 row-major [M,NN], bias=b0
// MODE 1: fused QKV, Ncols=3072: n>>10 selects {Q,K,V}; V stored [B][H][D][S]
// ---------------------------------------------------------------------------
#define SROWB 144
#define SBUF (128 * SROWB)      // 18432 per matrix per stage
#define SSTAGE (2 * SBUF)       // 36864
#define SNSTG 3
#define SNKS (KK / 64)          // 16

template <int MODE>
__global__ void __launch_bounds__(128) tc_gemm_kernel(
    const __half* __restrict__ A, const __half* __restrict__ Bt,
    const float* __restrict__ b0, const float* __restrict__ b1,
    const float* __restrict__ b2,
    void* __restrict__ o0, __half* __restrict__ o1, __half* __restrict__ o2)
{
    extern __shared__ char smc[];
    const uint32_t dat_u = smem_u32(smc);

    const int tid = threadIdx.x;
    const int wid = tid >> 5;
    const int lane = tid & 31;
    const int g = lane >> 2;
    const int t = lane & 3;
    const int wm = wid >> 1;     // 0..1
    const int wn = wid & 1;      // 0..1
    const int bm = blockIdx.y * 128;
    const int bn = blockIdx.x * 128;

    const int lq = tid & 7;
    const int lr = tid >> 3;     // 0..15

    const uint32_t aoff = (uint32_t)((wm * 64 + (lane & 15)) * SROWB + ((lane >> 4) << 4));
    const uint32_t boff = (uint32_t)((wn * 64 + ((lane >> 4) << 3) + (lane & 7)) * SROWB
                                     + (((lane >> 3) & 1) << 4));

    float acc[4][8][4];
#pragma unroll
    for (int mt = 0; mt < 4; mt++)
#pragma unroll
        for (int nt = 0; nt < 8; nt++)
#pragma unroll
            for (int r = 0; r < 4; r++) acc[mt][nt][r] = 0.f;

    // prologue: stages 0,1
#pragma unroll
    for (int s = 0; s < SNSTG - 1; ++s) {
        const uint32_t sb = dat_u + s * SSTAGE;
        const int kof = s * 64;
#pragma unroll
        for (int i = 0; i < 8; ++i) {
            int row = lr + i * 16;
            cp16(sb + row * SROWB + lq * 16, A + (size_t)(bm + row) * KK + kof + lq * 8);
            cp16(sb + SBUF + row * SROWB + lq * 16, Bt + (size_t)(bn + row) * KK + kof + lq * 8);
        }
        asm volatile("cp.async.commit_group;" ::: "memory");
    }

    for (int ks = 0; ks < SNKS; ++ks) {
        asm volatile("cp.async.wait_group %0;" :: "n"(SNSTG - 2) : "memory");
        __syncthreads();

        const uint32_t aB = dat_u + (ks % SNSTG) * SSTAGE;
        const uint32_t bB = aB + SBUF;

        // fragment double-buffer; preload k2=0 first
        uint32_t af[2][4][4], bf[2][4][4];
#pragma unroll
        for (int mt = 0; mt < 4; mt++)
            ldm4(af[0][mt], aB + aoff + mt * (16 * SROWB));
#pragma unroll
        for (int p = 0; p < 4; p++)
            ldm4(bf[0][p], bB + boff + p * (16 * SROWB));

        const int ldk = ks + SNSTG - 1;
        const bool dold = (ldk < SNKS);
        const uint32_t sb = dat_u + (ldk % SNSTG) * SSTAGE;
        const int kof = ldk * 64;

#pragma unroll
        for (int k2 = 0; k2 < 4; ++k2) {
            const int cur = k2 & 1;
            const int nxt = cur ^ 1;
            if (k2 < 3) {   // prefetch next k-step's fragments before MMAs
#pragma unroll
                for (int mt = 0; mt < 4; mt++)
                    ldm4(af[nxt][mt], aB + aoff + mt * (16 * SROWB) + (k2 + 1) * 32);
#pragma unroll
                for (int p = 0; p < 4; p++)
                    ldm4(bf[nxt][p], bB + boff + p * (16 * SROWB) + (k2 + 1) * 32);
            }
            // interleave 4 of the 16 next-stage cp.async ops per k2 step
            if (dold) {
#pragma unroll
                for (int i = 2 * k2; i < 2 * k2 + 2; ++i) {
                    int row = lr + i * 16;
                    cp16(sb + row * SROWB + lq * 16, A + (size_t)(bm + row) * KK + kof + lq * 8);
                    cp16(sb + SBUF + row * SROWB + lq * 16, Bt + (size_t)(bn + row) * KK + kof + lq * 8);
                }
            }
#pragma unroll
            for (int mt = 0; mt < 4; mt++)
#pragma unroll
                for (int p = 0; p < 4; p++) {
                    mma_f16(acc[mt][2 * p],     af[cur][mt], bf[cur][p] + 0);
                    mma_f16(acc[mt][2 * p + 1], af[cur][mt], bf[cur][p] + 2);
                }
        }
        asm volatile("cp.async.commit_group;" ::: "memory");   // ALWAYS (FIFO count)
    }

    // epilogue
#pragma unroll
    for (int mt = 0; mt < 4; mt++) {
#pragma unroll
        for (int half_ = 0; half_ < 2; half_++) {
            int m = bm + wm * 64 + mt * 16 + g + half_ * 8;
            int b = m >> 11;
            int s = m & 2047;
#pragma unroll
            for (int nt = 0; nt < 8; nt++) {
                int n = bn + wn * 64 + nt * 8 + 2 * t;
                float v0 = acc[mt][nt][half_ * 2 + 0];
                float v1 = acc[mt][nt][half_ * 2 + 1];
                if (MODE == 0) {
                    v0 += __ldg(&b0[n]); v1 += __ldg(&b0[n + 1]);
                    float* op = (float*)o0 + (size_t)m * NN + n;
                    *(float2*)op = make_float2(v0, v1);
                } else {
                    int which = n >> 10;
                    int nh = n & 1023;
                    int h = nh >> 6, d0 = nh & 63;
                    const float* bptr = which == 0 ? b0 : (which == 1 ? b1 : b2);
                    v0 += __ldg(&bptr[nh]); v1 += __ldg(&bptr[nh + 1]);
                    if (which == 2) {   // V transposed [b][h][d][s]
                        size_t bhd = (((size_t)b * HH + h) * DD + d0) * SS + s;
                        o2[bhd] = __float2half_rn(v0);
                        o2[bhd + SS] = __float2half_rn(v1);
                    } else {
                        __half* dst = which == 0 ? (__half*)o0 : o1;
                        __half* op = dst + (((size_t)b * HH + h) * SS + s) * DD + d0;
                        *(__half2*)op = __floats2half2_rn(v0, v1);
                    }
                }
            }
        }
    }
}

// ---------------------------------------------------------------------------
// prep kernels
// ---------------------------------------------------------------------------
__global__ void cvt_half_kernel(const float4* __restrict__ in, __half2* __restrict__ outp, int n4)
{
    for (int i = blockIdx.x * blockDim.x + threadIdx.x; i < n4; i += gridDim.x * blockDim.x) {
        float4 v = in[i];
        outp[2 * i]     = __floats2half2_rn(v.x, v.y);
        outp[2 * i + 1] = __floats2half2_rn(v.z, v.w);
    }
}

// fused QKV weight transpose: z in [0,48) -> which=z>>4 selects Wq/Wk/Wv,
// b=z&15 is the head. in fp32 [16][E][D] -> out half [which][16][D][E]
__global__ void transpose3_h_kernel(const float* __restrict__ wq,
                                    const float* __restrict__ wk,
                                    const float* __restrict__ wv,
                                    __half* __restrict__ outp)
{
    __shared__ float tile[32][33];
    const int z = blockIdx.z;
    const int which = z >> 4;
    const int b = z & 15;
    const float* in = (which == 0 ? wq : (which == 1 ? wk : wv));
    const int c0 = blockIdx.x * 32, r0 = blockIdx.y * 32;
    const int tx = threadIdx.x, ty = threadIdx.y;
    const float* inb = in + (size_t)b * EE * DD;
#pragma unroll
    for (int j = 0; j < 32; j += 8)
        tile[ty + j][tx] = inb[(size_t)(r0 + ty + j) * DD + c0 + tx];
    __syncthreads();
    __half* ob = outp + (size_t)z * DD * EE;
#pragma unroll
    for (int j = 0; j < 32; j += 8)
        ob[(size_t)(c0 + ty + j) * EE + r0 + tx] = __float2half_rn(tile[tx][ty + j]);
}

// in fp32 [R][C] -> out half [C][R]  (Wp)
__global__ void transpose_h_kernel(const float* __restrict__ in, __half* __restrict__ outp,
                                   int R, int C)
{
    __shared__ float tile[32][33];
    const int c0 = blockIdx.x * 32, r0 = blockIdx.y * 32;
    const int tx = threadIdx.x, ty = threadIdx.y;
#pragma unroll
    for (int j = 0; j < 32; j += 8)
        tile[ty + j][tx] = in[(size_t)(r0 + ty + j) * C + c0 + tx];
    __syncthreads();
#pragma unroll
    for (int j = 0; j < 32; j += 8)
        outp[(size_t)(c0 + ty + j) * R + r0 + tx] = __float2half_rn(tile[tx][ty + j]);
}

// ---------------------------------------------------------------------------
// Flash attention (causal) fp16 mma. Br=128, Bc=64, 256 threads (8 warps,
// 16 rows each). Q frags in registers; score C-frags reused as PV A-frags.
// K/Vt double-buffered cp.async. smem rows 144B.  (unchanged from R13)
// ---------------------------------------------------------------------------
#define FROWB 144
#define FTILE (64 * FROWB)      // 9216  (one 64-row K or Vt tile)
#define QTILE (128 * FROWB)     // 18432

__global__ void __launch_bounds__(256) flash_mma_kernel(
    const __half* __restrict__ q, const __half* __restrict__ k,
    const __half* __restrict__ vt, __half* __restrict__ outp)
{
    extern __shared__ char smc[];
    const uint32_t smb = smem_u32(smc);
    const uint32_t QsB = smb;
    const uint32_t KB0 = smb + QTILE;    // buffers: [K|Vt] x2

    const int qi = blockIdx.x;           // 0..15, rows [128qi, 128qi+128)
    const int bh = blockIdx.y;
    const size_t base = (size_t)bh * SS * DD;
    const int tid = threadIdx.x;
    const int w = tid >> 5;
    const int lane = tid & 31;
    const int g = lane >> 2;
    const int t = tid & 3;
    const int qr0 = qi * 128;
    const int r0g = w * 16 + g;          // local row of c0/c1; +8 for c2/c3
    const int nj = 2 * qi + 2;           // number of 64-wide K tiles

    const uint32_t qoff = (uint32_t)((w * 16 + (lane & 15)) * FROWB + ((lane >> 4) << 4));
    const uint32_t kvoff = (uint32_t)(((((lane >> 4) << 3) + (lane & 7)) * FROWB)
                                      + (((lane >> 3) & 1) << 4));

    // load Q tile (128 rows)
    for (int idx = tid; idx < 128 * 8; idx += 256) {
        int r = idx >> 3, qc = idx & 7;
        *(uint4*)(smc + r * FROWB + qc * 16) =
            *(const uint4*)(q + base + (size_t)(qr0 + r) * DD + qc * 8);
    }

    // prefetch K/Vt tile j=0 into buffer 0
    {
        const uint32_t kb = KB0, vb = KB0 + FTILE;
        for (int idx = tid; idx < 128 * 8; idx += 256) {
            int m = idx >> 3, qc = idx & 7;
            if (m < 64)
                cp16(kb + m * FROWB + qc * 16, k + base + (size_t)m * DD + qc * 8);
            else
                cp16(vb + (m - 64) * FROWB + qc * 16, vt + base + (size_t)(m - 64) * SS + qc * 8);
        }
        asm volatile("cp.async.commit_group;" ::: "memory");
    }
    __syncthreads();   // Q visible

    uint32_t qf[4][4];
#pragma unroll
    for (int ks = 0; ks < 4; ks++) ldm4(qf[ks], QsB + qoff + ks * 32);

    float o[8][4];
#pragma unroll
    for (int dt = 0; dt < 8; dt++)
#pragma unroll
        for (int r = 0; r < 4; r++) o[dt][r] = 0.f;
    float m0 = -1e30f, m1 = -1e30f, l0 = 0.f, l1 = 0.f;
    const float sc = 0.125f * 1.4426950408889634f;

    for (int j = 0; j < nj; ++j) {
        asm volatile("cp.async.wait_group 0;" ::: "memory");
        __syncthreads();
        const uint32_t kb = KB0 + (j & 1) * 2 * FTILE;
        const uint32_t vb = kb + FTILE;

        if (j + 1 < nj) {   // prefetch next tile
            const uint32_t kb2 = KB0 + ((j + 1) & 1) * 2 * FTILE;
            const uint32_t vb2 = kb2 + FTILE;
            const size_t koff = base + (size_t)(j + 1) * 64 * DD;
            const size_t voff = base + (size_t)(j + 1) * 64;
            for (int idx = tid; idx < 128 * 8; idx += 256) {
                int m = idx >> 3, qc = idx & 7;
                if (m < 64)
                    cp16(kb2 + m * FROWB + qc * 16, k + koff + (size_t)m * DD + qc * 8);
                else
                    cp16(vb2 + (m - 64) * FROWB + qc * 16, vt + voff + (size_t)(m - 64) * SS + qc * 8);
            }
            asm volatile("cp.async.commit_group;" ::: "memory");
        }

        // ---- S = Q K^T ----
        float sa[8][4];
#pragma unroll
        for (int nt = 0; nt < 8; nt++)
#pragma unroll
            for (int r = 0; r < 4; r++) sa[nt][r] = 0.f;
#pragma unroll
        for (int ks = 0; ks < 4; ++ks) {
#pragma unroll
            for (int p = 0; p < 4; p++) {
                uint32_t kf[4];
                ldm4(kf, kb + kvoff + p * (16 * FROWB) + ks * 32);
                mma_f16(sa[2 * p],     qf[ks], kf + 0);
                mma_f16(sa[2 * p + 1], qf[ks], kf + 2);
            }
        }

        // ---- fragment softmax ----
        const bool maskT = (j >= 2 * qi);   // only last two tiles touch diagonal
        const int row0 = r0g;               // local row (c0/c1)
        const int colb = (j - 2 * qi) * 64; // local col base for diagonal tiles
        float mloc0 = -1e30f, mloc1 = -1e30f;
#pragma unroll
        for (int nt = 0; nt < 8; nt++) {
            sa[nt][0] *= sc; sa[nt][1] *= sc; sa[nt][2] *= sc; sa[nt][3] *= sc;
            if (maskT) {
                int col = colb + nt * 8 + 2 * t;
                if (col     > row0)     sa[nt][0] = -1e30f;
                if (col + 1 > row0)     sa[nt][1] = -1e30f;
                if (col     > row0 + 8) sa[nt][2] = -1e30f;
                if (col + 1 > row0 + 8) sa[nt][3] = -1e30f;
            }
            mloc0 = fmaxf(mloc0, fmaxf(sa[nt][0], sa[nt][1]));
            mloc1 = fmaxf(mloc1, fmaxf(sa[nt][2], sa[nt][3]));
        }
        mloc0 = fmaxf(mloc0, __shfl_xor_sync(0xffffffffu, mloc0, 1));
        mloc0 = fmaxf(mloc0, __shfl_xor_sync(0xffffffffu, mloc0, 2));
        mloc1 = fmaxf(mloc1, __shfl_xor_sync(0xffffffffu, mloc1, 1));
        mloc1 = fmaxf(mloc1, __shfl_xor_sync(0xffffffffu, mloc1, 2));

        float mn0 = fmaxf(m0, mloc0), mn1 = fmaxf(m1, mloc1);
        float al0 = ex2(m0 - mn0), al1 = ex2(m1 - mn1);
        float rs0 = 0.f, rs1 = 0.f;
#pragma unroll
        for (int nt = 0; nt < 8; nt++) {
            sa[nt][0] = ex2(sa[nt][0] - mn0);
            sa[nt][1] = ex2(sa[nt][1] - mn0);
            sa[nt][2] = ex2(sa[nt][2] - mn1);
            sa[nt][3] = ex2(sa[nt][3] - mn1);
            rs0 += sa[nt][0] + sa[nt][1];
            rs1 += sa[nt][2] + sa[nt][3];
        }
        rs0 += __shfl_xor_sync(0xffffffffu, rs0, 1);
        rs0 += __shfl_xor_sync(0xffffffffu, rs0, 2);
        rs1 += __shfl_xor_sync(0xffffffffu, rs1, 1);
        rs1 += __shfl_xor_sync(0xffffffffu, rs1, 2);
        l0 = l0 * al0 + rs0;
        l1 = l1 * al1 + rs1;
        m0 = mn0; m1 = mn1;
#pragma unroll
        for (int dt = 0; dt < 8; dt++) {
            o[dt][0] *= al0; o[dt][1] *= al0;
            o[dt][2] *= al1; o[dt][3] *= al1;
        }

        // ---- O += P V : score C-frag is the A-frag ----
#pragma unroll
        for (int ks = 0; ks < 4; ++ks) {
            uint32_t pf[4];
            pf[0] = packh2(sa[2 * ks][0],     sa[2 * ks][1]);
            pf[1] = packh2(sa[2 * ks][2],     sa[2 * ks][3]);
            pf[2] = packh2(sa[2 * ks + 1][0], sa[2 * ks + 1][1]);
            pf[3] = packh2(sa[2 * ks + 1][2], sa[2 * ks + 1][3]);
#pragma unroll
            for (int p = 0; p < 4; p++) {
                uint32_t vf[4];
                ldm4(vf, vb + kvoff + p * (16 * FROWB) + ks * 32);
                mma_f16(o[2 * p],     pf, vf + 0);
                mma_f16(o[2 * p + 1], pf, vf + 2);
            }
        }
    }

    // epilogue: normalize, write half to [B, S, H*D]
    const int b = bh >> 4;
    const int h = bh & 15;
    const float inv0 = 1.f / l0, inv1 = 1.f / l1;
    const int grow0 = qr0 + r0g, grow1 = grow0 + 8;
#pragma unroll
    for (int nt = 0; nt < 8; nt++) {
        int d = nt * 8 + 2 * t;
        size_t ob0 = ((size_t)b * SS + grow0) * EE + h * 64 + d;
        size_t ob1 = ((size_t)b * SS + grow1) * EE + h * 64 + d;
        *(__half2*)&outp[ob0] = __floats2half2_rn(o[nt][0] * inv0, o[nt][1] * inv0);
        *(__half2*)&outp[ob1] = __floats2half2_rn(o[nt][2] * inv1, o[nt][3] * inv1);
    }
}

// ---------------------------------------------------------------------------
extern "C" void kernel_launch(void* const* d_in, const int* in_sizes, int n_in,
                              void* d_out, int out_size)
{
    const float* x  = (const float*)d_in[0];
    const float* Wq = (const float*)d_in[1];
    const float* bq = (const float*)d_in[2];
    const float* Wk = (const float*)d_in[3];
    const float* bk = (const float*)d_in[4];
    const float* Wv = (const float*)d_in[5];
    const float* bv = (const float*)d_in[6];
    const float* Wp = (const float*)d_in[7];
    const float* bp = (const float*)d_in[8];
    float* out = (float*)d_out;

    __half *qp, *kp, *vp, *ap, *xap, *wtp, *wt3p;
    cudaGetSymbolAddress((void**)&qp, g_q);
    cudaGetSymbolAddress((void**)&kp, g_k);
    cudaGetSymbolAddress((void**)&vp, g_v);
    cudaGetSymbolAddress((void**)&ap, g_attn);
    cudaGetSymbolAddress((void**)&xap, g_xa);
    cudaGetSymbolAddress((void**)&wtp, g_wt);
    cudaGetSymbolAddress((void**)&wt3p, g_wt3);

    const int gemm_smem = SNSTG * SSTAGE;                  // 110592
    cudaFuncSetAttribute(tc_gemm_kernel<0>, cudaFuncAttributeMaxDynamicSharedMemorySize, gemm_smem);
    cudaFuncSetAttribute(tc_gemm_kernel<1>, cudaFuncAttributeMaxDynamicSharedMemorySize, gemm_smem);
    const int fl_smem = QTILE + 4 * FTILE;                 // 55296
    cudaFuncSetAttribute(flash_mma_kernel, cudaFuncAttributeMaxDynamicSharedMemorySize, fl_smem);

    cvt_half_kernel<<<1024, 256>>>((const float4*)x, (__half2*)xap, MM * KK / 4);

    dim3 tb(32, 8);
    transpose3_h_kernel<<<dim3(2, 32, 48), tb>>>(Wq, Wk, Wv, wt3p);
    transpose_h_kernel<<<dim3(32, 32, 1), tb>>>(Wp, wtp, EE, EE);

    // fused QKV: N = 3072
    tc_gemm_kernel<1><<<dim3(24, 64), 128, gemm_smem>>>(
        xap, wt3p, bq, bk, bv, qp, kp, vp);

    dim3 fg(SS / 128, BB * HH);   // (16, 64)
    flash_mma_kernel<<<fg, 256, fl_smem>>>(qp, kp, vp, ap);

    // output projection
    tc_gemm_kernel<0><<<dim3(8, 64), 128, gemm_smem>>>(
        ap, wtp, bp, bp, bp, out, nullptr, nullptr);
}